// round 15
// baseline (speedup 1.0000x reference)
#include <cuda_runtime.h>
#include <cstdint>

// HiPPO-LegS bilinear discretization + sequential scan, N=256, L=1024, ALPHA=0.5.
//
// With K = 2k, w_i = 1/(K+i+1), aK = 1:
//   u_i = (K-i) w_i,  diag_i = 2K w_i - 1,
//   Ad[i][j] = b_i * c_j * prod_{j<m<i} u_m  (i>j),  b_i = -r_i w_i,  c_j = 2K r_j w_j
//   Bd[i]    = 2 r_i w_i * prod_{m<i} u_m
// Step (t = k-1):  Z_{i+1} = u_i Z_i + v_i, v_i = 2 r_i w_i (K c_i + f r_i), Z_0 = 0
//                  c'_i = u_i c_i + w_i (r_i (2f - Z_i) - c_i)
//
// SPLIT LAUNCHES (per-launch ncu attribution):
//   hippo_recur<<<1,32>>>   systolic one-warp recurrence + y
//   hippo_gbt<<<1024,64>>>  GBT_A/GBT_B via smem staging + cp.async.bulk (TMA)
//     stores, double-buffered 8KB chunks — replaces the per-thread STG path
//     that both prior variants pegged at ~600 GB/s effective.
//
// Output layout (flattened tuple): [c_all | y_all | GBT_A | GBT_B]

#define HP_L 1024
#define HP_N 256

#define OUT_C  0
#define OUT_Y  262144
#define OUT_GA 263168
#define OUT_GB 67372032

__device__ __forceinline__ uint32_t smem_u32(const void* p) {
    uint32_t a;
    asm("{ .reg .u64 t; cvta.to.shared.u64 t, %1; cvt.u32.u64 %0, t; }" : "=r"(a) : "l"(p));
    return a;
}

// -------- systolic recurrence + y: one warp --------
__global__ void __launch_bounds__(32) hippo_recur(
    const float* __restrict__ f,
    const float* __restrict__ init_state,
    const float* __restrict__ Bvec,
    float* __restrict__ out)
{
    __shared__ float s_f[HP_L];
    const int lane = threadIdx.x;
    #pragma unroll
    for (int q = 0; q < HP_L / 32; q++) s_f[lane + 32 * q] = f[lane + 32 * q];
    __syncwarp();

    float c[8], r[8], fi[8], fi1[8];
    #pragma unroll
    for (int e = 0; e < 8; e++) {
        int i = lane * 8 + e;
        r[e]   = Bvec[i];
        c[e]   = init_state[i];
        fi[e]  = (float)i;
        fi1[e] = (float)(i + 1);
    }
    float* out_c = out + OUT_C;
    float* out_y = out + OUT_Y;

    float Zreg = 0.0f, Yreg = 0.0f;
    float Kf = (float)(2 * (1 - lane));          // K = 2(b - lane + 1)

    for (int b = 0; b < HP_L + 31; b++) {
        float Zin = __shfl_up_sync(0xffffffffu, Zreg, 1);
        float yin = __shfl_up_sync(0xffffffffu, Yreg, 1);
        if (lane == 0) { Zin = 0.0f; yin = 0.0f; }

        const int t = b - lane;
        if (0 <= t && t < HP_L) {
            const float fv = s_f[t];
            const float f2 = fv + fv;            // 2f = hK

            float Zl = Zin, ysum = 0.0f;
            #pragma unroll
            for (int e = 0; e < 8; e++) {
                float w  = __frcp_rn(Kf + fi1[e]);              // 1/(K+i+1)
                float u  = (Kf - fi[e]) * w;                    // (K-i)w
                float fr = fv * r[e];
                float v  = (2.0f * r[e] * w) * fmaf(Kf, c[e], fr);
                float q2 = fmaf(r[e], f2 - Zl, -c[e]);          // r(2f-Z)-c
                float x  = fmaf(u, c[e], w * q2);
                Zl = fmaf(u, Zl, v);
                c[e] = x;
                ysum += x;
            }
            Zreg = Zl;
            Yreg = yin + ysum;

            float4* co = reinterpret_cast<float4*>(out_c + (size_t)t * HP_N + lane * 8);
            co[0] = make_float4(c[0], c[1], c[2], c[3]);
            co[1] = make_float4(c[4], c[5], c[6], c[7]);
            if (lane == 31) out_y[t] = Yreg;
        }
        Kf += 2.0f;
    }
}

// -------- GBT_A / GBT_B: smem staging + TMA bulk stores --------
#define CHUNK_ROWS 8
#define CHUNK_BYTES (CHUNK_ROWS * HP_N * 4)      // 8192
#define NCHUNK (HP_N / CHUNK_ROWS)               // 32

__global__ void __launch_bounds__(64) hippo_gbt(
    const float* __restrict__ Bvec,
    float* __restrict__ out)
{
    __shared__ float4 s_pack[HP_N];                               // {b_i, u_i, diag_i, -}
    __shared__ alignas(128) float4 s_buf[2][CHUNK_ROWS * (HP_N / 4)];  // 2 x 8KB
    __shared__ alignas(16)  float  s_gb[HP_N];                    // 1KB

    const int tid = threadIdx.x;
    const int k   = blockIdx.x + 1;              // 1..1024
    const float Kf = (float)(2 * k);             // K = 2k
    const float K2 = Kf + Kf;                    // 2K

    #pragma unroll
    for (int q = 0; q < HP_N / 64; q++) {
        int i = tid + 64 * q;
        float fi = (float)i;
        float w  = __frcp_rn(Kf + fi + 1.0f);
        float ri = Bvec[i];
        s_pack[i] = make_float4(-ri * w, (Kf - fi) * w, fmaf(K2, w, -1.0f), 0.0f);
    }
    __syncthreads();

    float4 cj;   // columns j = 4*tid..4*tid+3 : c_j = 2K r_j w_j
    {
        float4 r4 = reinterpret_cast<const float4*>(Bvec)[tid];
        float j0 = (float)(4 * tid);
        cj.x = K2 * r4.x * __frcp_rn(Kf + j0 + 1.0f);
        cj.y = K2 * r4.y * __frcp_rn(Kf + j0 + 2.0f);
        cj.z = K2 * r4.z * __frcp_rn(Kf + j0 + 3.0f);
        cj.w = K2 * r4.w * __frcp_rn(Kf + j0 + 4.0f);
    }

    char* ga_base = (char*)(out + OUT_GA) + (size_t)(k - 1) * (HP_N * HP_N * 4);
    char* gb_base = (char*)(out + OUT_GB) + (size_t)(k - 1) * (HP_N * 4);

    float4 W = make_float4(0.0f, 0.0f, 0.0f, 0.0f);  // 0 until activation at i==j
    float  G = 1.0f;                                  // tid 0: prod_{m<i} u_m
    const int rb = -4 * tid;

    for (int ch = 0; ch < NCHUNK; ch++) {
        float4* buf = s_buf[ch & 1];
        #pragma unroll
        for (int rr = 0; rr < CHUNK_ROWS; rr++) {
            int i = ch * CHUNK_ROWS + rr;
            float4 p = s_pack[i];
            int rel = i + rb;

            float4 v;
            v.x = (p.x * cj.x) * W.x;  if (rel == 0) v.x = p.z;
            v.y = (p.x * cj.y) * W.y;  if (rel == 1) v.y = p.z;
            v.z = (p.x * cj.z) * W.z;  if (rel == 2) v.z = p.z;
            v.w = (p.x * cj.w) * W.w;  if (rel == 3) v.w = p.z;
            buf[rr * (HP_N / 4) + tid] = v;

            W.x *= p.y;  if (rel == 0) W.x = 1.0f;
            W.y *= p.y;  if (rel == 1) W.y = 1.0f;
            W.z *= p.y;  if (rel == 2) W.z = 1.0f;
            W.w *= p.y;  if (rel == 3) W.w = 1.0f;

            if (tid == 0) { s_gb[i] = -2.0f * p.x * G; G *= p.y; }
        }
        __syncthreads();                              // chunk fully in smem
        if (tid == 0) {
            asm volatile("fence.proxy.async.shared::cta;" ::: "memory");
            asm volatile("cp.async.bulk.global.shared::cta.bulk_group [%0], [%1], %2;"
                         :: "l"(ga_base + (size_t)ch * CHUNK_BYTES),
                            "r"(smem_u32(buf)), "r"((uint32_t)CHUNK_BYTES) : "memory");
            asm volatile("cp.async.bulk.commit_group;" ::: "memory");
            asm volatile("cp.async.bulk.wait_group.read 1;" ::: "memory");  // parity buffer free
        }
        __syncthreads();                              // all threads see buffer-free
    }

    if (tid == 0) {
        asm volatile("fence.proxy.async.shared::cta;" ::: "memory");
        asm volatile("cp.async.bulk.global.shared::cta.bulk_group [%0], [%1], %2;"
                     :: "l"(gb_base), "r"(smem_u32(s_gb)), "r"((uint32_t)(HP_N * 4)) : "memory");
        asm volatile("cp.async.bulk.commit_group;" ::: "memory");
        asm volatile("cp.async.bulk.wait_group 0;" ::: "memory");
    }
}

extern "C" void kernel_launch(void* const* d_in, const int* in_sizes, int n_in,
                              void* d_out, int out_size) {
    const float* f  = (const float*)d_in[0];   // (L,1)
    const float* s0 = (const float*)d_in[1];   // (N,1) init_state
    // d_in[2] = A (unused: closed-form), d_in[3] = B = r
    const float* Bv = (const float*)d_in[3];
    float* out = (float*)d_out;

    hippo_recur<<<1, 32>>>(f, s0, Bv, out);
    hippo_gbt<<<HP_L, 64>>>(Bv, out);
}